// round 6
// baseline (speedup 1.0000x reference)
#include <cuda_runtime.h>
#include <cstddef>

// Grefenstette stack forward, closed-form reformulation.
//
//   s_t[j] = relu(d_j - relu(M_{j,t} - H_j)),  M_{j,t} = max_{j<tau<=t} G_tau
//     G_tau = P_tau - D_{tau-1},  H_j = P_j - D_j,  P = cumsum(u), D = cumsum(d)
//   w_t[j] = min(1, R_t[j]) - min(1, R_t[j+1]),  R = suffix-sum of s_t
//   out[t,b,:] = sum_j w_t[j] * v[j,b,:]
//
// K1: tiled, fully-coalesced fp64 scan (8 blocks x 16 batches, smem staging,
//     float4 stores of G/H/D [B][T]).
// K2: fused weights+gather, warp per 4 consecutive t's. Phase A runs the 4
//     warp-scan chunks as independent ILP chains; Phase B gathers.

#define TT 512
#define BB 128
#define EE 256

#define FULL 0xFFFFFFFFu

#define SB   16   // batches per scan block
#define TILE 128  // timesteps per scan tile

#define GW  8     // gather warps per block
#define TPW 4     // t's per gather warp

__device__ float g_G[BB][TT];
__device__ float g_H[BB][TT];
__device__ float g_D[BB][TT];

// ---------------------------------------------------------------------------
// Kernel 1: fp64 prefix sums. Grid = BB/SB blocks, 512 threads (16 warps).
// Warp w owns batch b0+w; lanes each carry 4 consecutive t's per tile.
// ---------------------------------------------------------------------------
__global__ __launch_bounds__(512) void scan_kernel(const float* __restrict__ u,
                                                   const float* __restrict__ d) {
    __shared__ float su[TILE][SB + 1];
    __shared__ float sd[TILE][SB + 1];

    const int tid  = threadIdx.x;
    const int wid  = tid >> 5;
    const int lane = tid & 31;
    const int b0   = blockIdx.x * SB;
    const int b    = b0 + wid;

    double carU = 0.0, carD = 0.0;  // batch carry (replicated per lane)

    for (int tile = 0; tile < TT / TILE; ++tile) {
        // Coalesced staging: 16 contiguous floats per t-row.
        #pragma unroll
        for (int p = 0; p < (TILE * SB) / 512; ++p) {
            const int idx = p * 512 + tid;
            const int c   = idx & (SB - 1);
            const int t   = idx >> 4;
            su[t][c] = u[(tile * TILE + t) * BB + b0 + c];
            sd[t][c] = d[(tile * TILE + t) * BB + b0 + c];
        }
        __syncthreads();

        // Thread-serial inclusive prefix over its 4 t's.
        float  dd[4];
        double pu[4], pd[4];
        double ru = 0.0, rd = 0.0;
        #pragma unroll
        for (int i = 0; i < 4; ++i) {
            const int t = lane * 4 + i;
            const float uu = su[t][wid];
            dd[i] = sd[t][wid];
            ru += (double)uu;  pu[i] = ru;
            rd += (double)dd[i]; pd[i] = rd;
        }

        // Warp inclusive scan of thread totals.
        double xu = ru, xd = rd;
        #pragma unroll
        for (int o = 1; o < 32; o <<= 1) {
            const double yu = __shfl_up_sync(FULL, xu, o);
            const double yd = __shfl_up_sync(FULL, xd, o);
            if (lane >= o) { xu += yu; xd += yd; }
        }
        double eu = __shfl_up_sync(FULL, xu, 1);
        double ed = __shfl_up_sync(FULL, xd, 1);
        if (lane == 0) { eu = 0.0; ed = 0.0; }

        const double totU = __shfl_sync(FULL, xu, 31);
        const double totD = __shfl_sync(FULL, xd, 31);

        // Emit G/H/D for 4 consecutive t's; coalesced float4 stores.
        float4 vG, vH, vD;
        float* pg = (float*)&vG; float* ph = (float*)&vH; float* pv = (float*)&vD;
        #pragma unroll
        for (int i = 0; i < 4; ++i) {
            const double P     = carU + eu + pu[i];
            const double Dcur  = carD + ed + pd[i];
            const double Dprev = Dcur - (double)dd[i];
            pg[i] = (float)(P - Dprev);
            ph[i] = (float)(P - Dcur);
            pv[i] = dd[i];
        }
        const int tg = tile * TILE + lane * 4;
        *reinterpret_cast<float4*>(&g_G[b][tg]) = vG;
        *reinterpret_cast<float4*>(&g_H[b][tg]) = vH;
        *reinterpret_cast<float4*>(&g_D[b][tg]) = vD;

        carU += totU;
        carD += totD;
        __syncthreads();  // protect smem for the next tile
    }
}

// ---------------------------------------------------------------------------
// Kernel 2: fused weights + gather. One warp per TPW consecutive t's.
// ---------------------------------------------------------------------------
__global__ __launch_bounds__(GW * 32, 5) void gather_kernel(
    const float* __restrict__ v, float* __restrict__ out) {
    const int tid   = threadIdx.x;
    const int warp  = tid >> 5;
    const int lane  = tid & 31;
    const int tbase = (blockIdx.x * GW + warp) * TPW;
    const int b     = blockIdx.y;

    const float4* __restrict__ v4 = reinterpret_cast<const float4*>(v);
    float4* __restrict__ o4       = reinterpret_cast<float4*>(out);

    // ---- Phase A: 4 independent chunk scans (ILP hides shuffle latency) ----
    float    wv[TPW];   // per-lane weight for slot (t_i - lane)
    unsigned mk[TPW];   // ballot of nonzero weights
    float    cA[TPW];   // carryAcc after chunk
    float    cM[TPW];   // carryM after chunk

    #pragma unroll
    for (int i = 0; i < TPW; ++i) {
        const int  t  = tbase + i;
        const int  j  = t - lane;
        const bool ok = (j >= 0);

        float m        = ok ? __ldg(&g_G[b][j]) : -1e30f;
        const float Hj = ok ? __ldg(&g_H[b][j]) : 0.f;
        const float Dj = ok ? __ldg(&g_D[b][j]) : 0.f;

        // Inclusive forward max-scan of G over lanes (lane 0 = slot t).
        #pragma unroll
        for (int o = 1; o < 32; o <<= 1) {
            const float x = __shfl_up_sync(FULL, m, o);
            if (lane >= o) m = fmaxf(m, x);
        }
        float Me = __shfl_up_sync(FULL, m, 1);
        if (lane == 0) Me = -1e30f;

        const float s = ok ? fmaxf(Dj - fmaxf(Me - Hj, 0.f), 0.f) : 0.f;

        // Inclusive forward sum-scan of s over lanes.
        float a = s;
        #pragma unroll
        for (int o = 1; o < 32; o <<= 1) {
            const float x = __shfl_up_sync(FULL, a, o);
            if (lane >= o) a += x;
        }
        const float accExc = a - s;
        wv[i] = fminf(a, 1.f) - fminf(accExc, 1.f);
        mk[i] = __ballot_sync(FULL, wv[i] > 0.f);
        cA[i] = __shfl_sync(FULL, a, 31);
        cM[i] = __shfl_sync(FULL, m, 31);
    }

    // ---- Phase B: gather per t ----
    #pragma unroll
    for (int i = 0; i < TPW; ++i) {
        const int t = tbase + i;

        float4 r0 = make_float4(0.f, 0.f, 0.f, 0.f);
        float4 r1 = make_float4(0.f, 0.f, 0.f, 0.f);

        unsigned mask = mk[i];
        while (mask) {
            const int src = __ffs(mask) - 1;
            mask &= mask - 1;
            const float wj = __shfl_sync(FULL, wv[i], src);
            const int   jj = t - src;
            const float4* vp = v4 + ((size_t)jj * BB + b) * (EE / 4);
            const float4 a0 = __ldg(vp + lane);
            const float4 a1 = __ldg(vp + lane + 32);
            r0.x = fmaf(wj, a0.x, r0.x);
            r0.y = fmaf(wj, a0.y, r0.y);
            r0.z = fmaf(wj, a0.z, r0.z);
            r0.w = fmaf(wj, a0.w, r0.w);
            r1.x = fmaf(wj, a1.x, r1.x);
            r1.y = fmaf(wj, a1.y, r1.y);
            r1.z = fmaf(wj, a1.z, r1.z);
            r1.w = fmaf(wj, a1.w, r1.w);
        }

        // Rare continuation: top-32 strengths summed to < 1 and deeper
        // slots exist. Warp-uniform branch; exact R3 chunk loop.
        if (cA[i] < 1.f && t >= 32) {
            float carryM   = cM[i];
            float carryAcc = cA[i];
            for (int jtop = t - 32; jtop >= 0 && carryAcc < 1.f; jtop -= 32) {
                const int  j  = jtop - lane;
                const bool ok = (j >= 0);

                float m        = ok ? __ldg(&g_G[b][j]) : -1e30f;
                const float Hj = ok ? __ldg(&g_H[b][j]) : 0.f;
                const float Dj = ok ? __ldg(&g_D[b][j]) : 0.f;

                #pragma unroll
                for (int o = 1; o < 32; o <<= 1) {
                    const float x = __shfl_up_sync(FULL, m, o);
                    if (lane >= o) m = fmaxf(m, x);
                }
                float Me = __shfl_up_sync(FULL, m, 1);
                if (lane == 0) Me = -1e30f;
                Me = fmaxf(Me, carryM);

                const float s = ok ? fmaxf(Dj - fmaxf(Me - Hj, 0.f), 0.f) : 0.f;

                float a = s;
                #pragma unroll
                for (int o = 1; o < 32; o <<= 1) {
                    const float x = __shfl_up_sync(FULL, a, o);
                    if (lane >= o) a += x;
                }
                const float accInc = carryAcc + a;
                const float accExc = accInc - s;
                const float w = fminf(accInc, 1.f) - fminf(accExc, 1.f);

                unsigned m2 = __ballot_sync(FULL, w > 0.f);
                while (m2) {
                    const int src = __ffs(m2) - 1;
                    m2 &= m2 - 1;
                    const float wj = __shfl_sync(FULL, w, src);
                    const int   jj = jtop - src;
                    const float4* vp = v4 + ((size_t)jj * BB + b) * (EE / 4);
                    const float4 a0 = __ldg(vp + lane);
                    const float4 a1 = __ldg(vp + lane + 32);
                    r0.x = fmaf(wj, a0.x, r0.x);
                    r0.y = fmaf(wj, a0.y, r0.y);
                    r0.z = fmaf(wj, a0.z, r0.z);
                    r0.w = fmaf(wj, a0.w, r0.w);
                    r1.x = fmaf(wj, a1.x, r1.x);
                    r1.y = fmaf(wj, a1.y, r1.y);
                    r1.z = fmaf(wj, a1.z, r1.z);
                    r1.w = fmaf(wj, a1.w, r1.w);
                }

                carryAcc = __shfl_sync(FULL, accInc, 31);
                carryM   = fmaxf(carryM, __shfl_sync(FULL, m, 31));
            }
        }

        float4* op = o4 + ((size_t)t * BB + b) * (EE / 4);
        op[lane]      = r0;
        op[lane + 32] = r1;
    }
}

extern "C" void kernel_launch(void* const* d_in, const int* in_sizes, int n_in,
                              void* d_out, int out_size) {
    const float* v = (const float*)d_in[0];  // [T,B,E]
    const float* u = (const float*)d_in[1];  // [T,B]
    const float* d = (const float*)d_in[2];  // [T,B]
    float* out     = (float*)d_out;          // [T,B,E]

    scan_kernel<<<BB / SB, 512>>>(u, d);

    dim3 ggrid(TT / (GW * TPW), BB);
    gather_kernel<<<ggrid, GW * 32>>>(v, out);
}

// round 7
// speedup vs baseline: 1.9219x; 1.9219x over previous
#include <cuda_runtime.h>
#include <cstddef>

// Grefenstette stack forward, closed-form reformulation.
//
//   s_t[j] = relu(d_j - relu(M_{j,t} - H_j)),  M_{j,t} = max_{j<tau<=t} G_tau
//     G_tau = P_tau - D_{tau-1},  H_j = P_j - D_j,  P = cumsum(u), D = cumsum(d)
//   w_t[j] = min(1, R_t[j]) - min(1, R_t[j+1]),  R = suffix-sum of s_t
//   out[t,b,:] = sum_j w_t[j] * v[j,b,:]
//
// K1: fp64 shuffle-scan prefix sums (block per batch) -> G,H,D [B][T].
// K2: fused weights+gather, warp per (t,b) (8192 blocks). The 8 warps of a
//     block share one smem staging of the 39 top slots they all scan.

#define TT 512
#define BB 128
#define EE 256

#define FULL 0xFFFFFFFFu
#define GW 8              // gather warps per block (consecutive t's, same b)
#define STAGE 40          // staged slots: [tbase-31, tbase+8) = 39, padded

__device__ float g_G[BB][TT];
__device__ float g_H[BB][TT];
__device__ float g_D[BB][TT];

// ---------------------------------------------------------------------------
// Kernel 1: fp64 prefix sums (shuffle scan, 2 syncs). One block per batch.
// ---------------------------------------------------------------------------
__global__ __launch_bounds__(TT) void scan_kernel(const float* __restrict__ u,
                                                  const float* __restrict__ d) {
    __shared__ double wsU[16];
    __shared__ double wsD[16];

    const int b    = blockIdx.x;
    const int t    = threadIdx.x;
    const int wid  = t >> 5;
    const int lane = t & 31;

    const float uv = u[t * BB + b];
    const float dv = d[t * BB + b];

    double xu = (double)uv;
    double xd = (double)dv;
    #pragma unroll
    for (int o = 1; o < 32; o <<= 1) {
        const double yu = __shfl_up_sync(FULL, xu, o);
        const double yd = __shfl_up_sync(FULL, xd, o);
        if (lane >= o) { xu += yu; xd += yd; }
    }
    if (lane == 31) { wsU[wid] = xu; wsD[wid] = xd; }
    __syncthreads();
    if (wid == 0) {
        double tu = (lane < 16) ? wsU[lane] : 0.0;
        double td = (lane < 16) ? wsD[lane] : 0.0;
        #pragma unroll
        for (int o = 1; o < 16; o <<= 1) {
            const double yu = __shfl_up_sync(FULL, tu, o);
            const double yd = __shfl_up_sync(FULL, td, o);
            if (lane >= o) { tu += yu; td += yd; }
        }
        if (lane < 16) { wsU[lane] = tu; wsD[lane] = td; }
    }
    __syncthreads();
    const double offU = (wid > 0) ? wsU[wid - 1] : 0.0;
    const double offD = (wid > 0) ? wsD[wid - 1] : 0.0;

    const double P  = xu + offU;
    const double Dc = xd + offD;

    g_G[b][t] = (float)(P - (Dc - (double)dv));  // P_t - D_{t-1}
    g_H[b][t] = (float)(P - Dc);                 // P_t - D_t
    g_D[b][t] = dv;
}

// ---------------------------------------------------------------------------
// Kernel 2: fused weights + gather. Warp per (t,b); grid (TT/GW, BB).
// First chunk reads block-shared smem staging of the top slots.
// ---------------------------------------------------------------------------
__global__ __launch_bounds__(GW * 32) void gather_kernel(
    const float* __restrict__ v, float* __restrict__ out) {
    __shared__ float sG[STAGE];
    __shared__ float sH[STAGE];
    __shared__ float sD[STAGE];

    const int tid   = threadIdx.x;
    const int warp  = tid >> 5;
    const int lane  = tid & 31;
    const int tbase = blockIdx.x * GW;
    const int t     = tbase + warp;
    const int b     = blockIdx.y;

    // Stage slots [lo, tbase+GW) of G/H/D — all first chunks live here.
    const int lo  = (tbase >= 31) ? tbase - 31 : 0;
    const int cnt = tbase + GW - lo;          // <= 39
    if (tid < cnt) {
        sG[tid] = g_G[b][lo + tid];
        sH[tid] = g_H[b][lo + tid];
        sD[tid] = g_D[b][lo + tid];
    }
    __syncthreads();

    const float4* __restrict__ v4 = reinterpret_cast<const float4*>(v);
    float4* __restrict__ o4       = reinterpret_cast<float4*>(out);

    // ---- First chunk: warp scan over slots t-31..t from smem ----
    const int  j  = t - lane;
    const bool ok = (j >= 0);
    const int  sj = j - lo;

    float m        = ok ? sG[sj] : -1e30f;
    const float Hj = ok ? sH[sj] : 0.f;
    const float Dj = ok ? sD[sj] : 0.f;

    // Inclusive forward max-scan of G over lanes (lane 0 = slot t).
    #pragma unroll
    for (int o = 1; o < 32; o <<= 1) {
        const float x = __shfl_up_sync(FULL, m, o);
        if (lane >= o) m = fmaxf(m, x);
    }
    float Me = __shfl_up_sync(FULL, m, 1);
    if (lane == 0) Me = -1e30f;

    const float s = ok ? fmaxf(Dj - fmaxf(Me - Hj, 0.f), 0.f) : 0.f;

    // Inclusive forward sum-scan of s over lanes.
    float a = s;
    #pragma unroll
    for (int o = 1; o < 32; o <<= 1) {
        const float x = __shfl_up_sync(FULL, a, o);
        if (lane >= o) a += x;
    }
    const float accExc = a - s;
    const float w0 = fminf(a, 1.f) - fminf(accExc, 1.f);

    float4 r0 = make_float4(0.f, 0.f, 0.f, 0.f);
    float4 r1 = make_float4(0.f, 0.f, 0.f, 0.f);

    unsigned mask = __ballot_sync(FULL, w0 > 0.f);
    while (mask) {
        const int src = __ffs(mask) - 1;
        mask &= mask - 1;
        const float wj = __shfl_sync(FULL, w0, src);
        const int   jj = t - src;
        const float4* vp = v4 + ((size_t)jj * BB + b) * (EE / 4);
        const float4 a0 = __ldg(vp + lane);
        const float4 a1 = __ldg(vp + lane + 32);
        r0.x = fmaf(wj, a0.x, r0.x);
        r0.y = fmaf(wj, a0.y, r0.y);
        r0.z = fmaf(wj, a0.z, r0.z);
        r0.w = fmaf(wj, a0.w, r0.w);
        r1.x = fmaf(wj, a1.x, r1.x);
        r1.y = fmaf(wj, a1.y, r1.y);
        r1.z = fmaf(wj, a1.z, r1.z);
        r1.w = fmaf(wj, a1.w, r1.w);
    }

    // ---- Rare continuation: deeper chunks from global (exact R3 loop) ----
    float carryAcc = __shfl_sync(FULL, a, 31);
    if (carryAcc < 1.f && t >= 32) {
        float carryM = __shfl_sync(FULL, m, 31);
        for (int jtop = t - 32; jtop >= 0 && carryAcc < 1.f; jtop -= 32) {
            const int  jc  = jtop - lane;
            const bool okc = (jc >= 0);

            float mc        = okc ? g_G[b][jc] : -1e30f;
            const float Hjc = okc ? g_H[b][jc] : 0.f;
            const float Djc = okc ? g_D[b][jc] : 0.f;

            #pragma unroll
            for (int o = 1; o < 32; o <<= 1) {
                const float x = __shfl_up_sync(FULL, mc, o);
                if (lane >= o) mc = fmaxf(mc, x);
            }
            float Mec = __shfl_up_sync(FULL, mc, 1);
            if (lane == 0) Mec = -1e30f;
            Mec = fmaxf(Mec, carryM);

            const float sc = okc ? fmaxf(Djc - fmaxf(Mec - Hjc, 0.f), 0.f) : 0.f;

            float ac = sc;
            #pragma unroll
            for (int o = 1; o < 32; o <<= 1) {
                const float x = __shfl_up_sync(FULL, ac, o);
                if (lane >= o) ac += x;
            }
            const float accInc = carryAcc + ac;
            const float accEx2 = accInc - sc;
            const float wc = fminf(accInc, 1.f) - fminf(accEx2, 1.f);

            unsigned m2 = __ballot_sync(FULL, wc > 0.f);
            while (m2) {
                const int src = __ffs(m2) - 1;
                m2 &= m2 - 1;
                const float wj = __shfl_sync(FULL, wc, src);
                const int   jj = jtop - src;
                const float4* vp = v4 + ((size_t)jj * BB + b) * (EE / 4);
                const float4 a0 = __ldg(vp + lane);
                const float4 a1 = __ldg(vp + lane + 32);
                r0.x = fmaf(wj, a0.x, r0.x);
                r0.y = fmaf(wj, a0.y, r0.y);
                r0.z = fmaf(wj, a0.z, r0.z);
                r0.w = fmaf(wj, a0.w, r0.w);
                r1.x = fmaf(wj, a1.x, r1.x);
                r1.y = fmaf(wj, a1.y, r1.y);
                r1.z = fmaf(wj, a1.z, r1.z);
                r1.w = fmaf(wj, a1.w, r1.w);
            }

            carryAcc = __shfl_sync(FULL, accInc, 31);
            carryM   = fmaxf(carryM, __shfl_sync(FULL, mc, 31));
        }
    }

    float4* op = o4 + ((size_t)t * BB + b) * (EE / 4);
    op[lane]      = r0;
    op[lane + 32] = r1;
}

extern "C" void kernel_launch(void* const* d_in, const int* in_sizes, int n_in,
                              void* d_out, int out_size) {
    const float* v = (const float*)d_in[0];  // [T,B,E]
    const float* u = (const float*)d_in[1];  // [T,B]
    const float* d = (const float*)d_in[2];  // [T,B]
    float* out     = (float*)d_out;          // [T,B,E]

    scan_kernel<<<BB, TT>>>(u, d);

    dim3 ggrid(TT / GW, BB);
    gather_kernel<<<ggrid, GW * 32>>>(v, out);
}